// round 9
// baseline (speedup 1.0000x reference)
#include <cuda_runtime.h>

#define REPS 1e-4f
#define GYP  148
#define NBLK (4 * GYP)     // 592 blocks, 4/SM

// Scratch (no allocations allowed). Zero-init at load; last finisher resets
// everything so graph replays see clean state.
__device__ float    g_M[25 * 32];  // each accumulator on its own 128B line
__device__ unsigned g_cnt;         // phase-1 arrivals
__device__ unsigned g_done;        // phase-3 completions

__device__ __forceinline__ unsigned ld_cg_u32(const unsigned* p) {
    unsigned v;
    asm volatile("ld.global.cg.u32 %0, [%1];" : "=r"(v) : "l"(p));
    return v;
}

// ---------------------------------------------------------------------------
// Single fused persistent kernel.
//  Phase 1: M = W1^T X W1 banded reduction (R4 body, byte-identical math)
//  Sync:    atomic arrivals; per-block spin on PLAIN .cg load (no atomics)
//  Phase 2: every block: thread 0 runs 5x5 Jacobi in SMEM scratch -> sA5
//  Phase 3: each thread computes its own H slice locally, writes its band
// ---------------------------------------------------------------------------
__global__ __launch_bounds__(256, 4) void k_all(const float* __restrict__ X,
                                                const float* __restrict__ W1,
                                                const float* __restrict__ W2,
                                                float* __restrict__ out) {
    const int tid = threadIdx.x;
    const int bid = blockIdx.x;

    // ---------------- Phase 1: banded projection (R4 body) ----------------
    const int cg   = bid & 3;
    const int band = bid >> 2;
    const int j0   = cg * 1024 + tid * 4;
    const int r0   = (band * 4096) / GYP;
    const int r1   = ((band + 1) * 4096) / GYP;
    const int R    = r1 - r0;                     // 27 or 28

    __shared__ float sW1[28 * 5];
    __shared__ float sM[8][25];
    __shared__ float sB[25], sU[25], sA5[25];
    if (tid < R * 5) sW1[tid] = W1[r0 * 5 + tid];
    __syncthreads();

    float tacc[4][5];
#pragma unroll
    for (int cc = 0; cc < 4; cc++)
#pragma unroll
        for (int a = 0; a < 5; a++) tacc[cc][a] = 0.f;

    const float* Xb = X + (size_t)r0 * 4096 + j0;
    int r = 0;
    for (; r + 4 <= R; r += 4) {
        const float4 x0 = *reinterpret_cast<const float4*>(Xb + (size_t)(r + 0) * 4096);
        const float4 x1 = *reinterpret_cast<const float4*>(Xb + (size_t)(r + 1) * 4096);
        const float4 x2 = *reinterpret_cast<const float4*>(Xb + (size_t)(r + 2) * 4096);
        const float4 x3 = *reinterpret_cast<const float4*>(Xb + (size_t)(r + 3) * 4096);
        const float4 xs[4] = {x0, x1, x2, x3};
#pragma unroll
        for (int k = 0; k < 4; k++) {
            const float xv[4] = {xs[k].x, xs[k].y, xs[k].z, xs[k].w};
            float w[5];
#pragma unroll
            for (int a = 0; a < 5; a++) w[a] = sW1[(r + k) * 5 + a];
#pragma unroll
            for (int cc = 0; cc < 4; cc++)
#pragma unroll
                for (int a = 0; a < 5; a++) tacc[cc][a] += xv[cc] * w[a];
        }
    }
    for (; r < R; r++) {
        const float4 x = *reinterpret_cast<const float4*>(Xb + (size_t)r * 4096);
        const float xv[4] = {x.x, x.y, x.z, x.w};
        float w[5];
#pragma unroll
        for (int a = 0; a < 5; a++) w[a] = sW1[r * 5 + a];
#pragma unroll
        for (int cc = 0; cc < 4; cc++)
#pragma unroll
            for (int a = 0; a < 5; a++) tacc[cc][a] += xv[cc] * w[a];
    }

    // Fold with W1[j,b] once per thread
    float mp[5][5];
#pragma unroll
    for (int a = 0; a < 5; a++)
#pragma unroll
        for (int b = 0; b < 5; b++) mp[a][b] = 0.f;
#pragma unroll
    for (int cc = 0; cc < 4; cc++) {
        float w1j[5];
#pragma unroll
        for (int b = 0; b < 5; b++) w1j[b] = __ldg(W1 + (j0 + cc) * 5 + b);
#pragma unroll
        for (int a = 0; a < 5; a++)
#pragma unroll
            for (int b = 0; b < 5; b++) mp[a][b] += tacc[cc][a] * w1j[b];
    }

    // Block reduce 25 values -> 25 padded global atomics
    const int lane = tid & 31, warp = tid >> 5;
#pragma unroll
    for (int e = 0; e < 25; e++) {
        float v = mp[e / 5][e % 5];
#pragma unroll
        for (int o = 16; o > 0; o >>= 1) v += __shfl_down_sync(0xffffffffu, v, o);
        if (lane == 0) sM[warp][e] = v;
    }
    __syncthreads();
    if (tid < 25) {
        float v = 0.f;
#pragma unroll
        for (int wq = 0; wq < 8; wq++) v += sM[wq][tid];
        atomicAdd(&g_M[tid * 32], v);
    }
    if (tid == 0) {
        __threadfence();
        atomicAdd(&g_cnt, 1u);
    }

    // ------ Phase-3 prologue loads (independent of A5): issue pre-spin ------
    const int jh    = bid & 1;
    const int band2 = bid >> 1;
    const int jo    = jh * 1024 + tid * 4;
    const int o0    = (band2 * 2048) / (NBLK / 2);
    const int o1    = ((band2 + 1) * 2048) / (NBLK / 2);
    float w2j[5][4];
#pragma unroll
    for (int b2 = 0; b2 < 5; b2++)
#pragma unroll
        for (int cc = 0; cc < 4; cc++)
            w2j[b2][cc] = __ldg(W2 + b2 * 2048 + jo + cc);

    // ---------------- Spin: plain .cg load, no atomic storm ----------------
    if (tid == 0) {
        while (ld_cg_u32(&g_cnt) < (unsigned)NBLK) __nanosleep(100);
        __threadfence();
    }
    __syncthreads();

    // ---------------- Phase 2: Jacobi in SMEM scratch (thread 0) -----------
    if (tid == 0) {
        float m[5][5];
#pragma unroll
        for (int a = 0; a < 5; a++)
#pragma unroll
            for (int c = 0; c < 5; c++) m[a][c] = __ldcg(&g_M[(a * 5 + c) * 32]);

        float tr = 0.f;
#pragma unroll
        for (int a = 0; a < 5; a++)
#pragma unroll
            for (int c = 0; c < 5; c++) {
                float s = 0.f;
#pragma unroll
                for (int k = 0; k < 5; k++) s += m[a][k] * m[c][k];
                sB[a * 5 + c] = s;
                sU[a * 5 + c] = (a == c) ? 1.f : 0.f;
                if (a == c) tr += s;
            }
        const float skip_tol = 1e-7f * tr;

#pragma unroll 1
        for (int sweep = 0; sweep < 5; sweep++) {
#pragma unroll
            for (int p = 0; p < 4; p++) {
#pragma unroll
                for (int q = p + 1; q < 5; q++) {
                    const float apq = sB[p * 5 + q];
                    if (fabsf(apq) > skip_tol) {
                        const float tau = (sB[q * 5 + q] - sB[p * 5 + p]) / (2.f * apq);
                        const float t   = copysignf(1.f, tau) / (fabsf(tau) + sqrtf(1.f + tau * tau));
                        const float c   = rsqrtf(1.f + t * t);
                        const float s   = t * c;
#pragma unroll
                        for (int k = 0; k < 5; k++) {
                            const float bkp = sB[k * 5 + p], bkq = sB[k * 5 + q];
                            sB[k * 5 + p] = c * bkp - s * bkq;
                            sB[k * 5 + q] = s * bkp + c * bkq;
                        }
#pragma unroll
                        for (int k = 0; k < 5; k++) {
                            const float bpk = sB[p * 5 + k], bqk = sB[q * 5 + k];
                            sB[p * 5 + k] = c * bpk - s * bqk;
                            sB[q * 5 + k] = s * bpk + c * bqk;
                            const float ukp = sU[k * 5 + p], ukq = sU[k * 5 + q];
                            sU[k * 5 + p] = c * ukp - s * ukq;
                            sU[k * 5 + q] = s * ukp + c * ukq;
                        }
                    }
                }
            }
        }

        float f[5];
#pragma unroll
        for (int d = 0; d < 5; d++) {
            const float lam = fmaxf(sB[d * 5 + d], 0.f);
            f[d] = fmaxf(sqrtf(lam), REPS) - REPS;
        }
#pragma unroll
        for (int a = 0; a < 5; a++)
#pragma unroll
            for (int c = 0; c < 5; c++) {
                float s = 0.f;
#pragma unroll
                for (int d = 0; d < 5; d++) s += sU[a * 5 + d] * f[d] * sU[c * 5 + d];
                sA5[a * 5 + c] = s;
            }
    }
    __syncthreads();

    // ---------------- Phase 3: z = W2^T (A5 W2) + EPS*I --------------------
    float hv[5][4];
#pragma unroll
    for (int a = 0; a < 5; a++)
#pragma unroll
        for (int cc = 0; cc < 4; cc++) {
            float s = 0.f;
#pragma unroll
            for (int b2 = 0; b2 < 5; b2++) s += sA5[a * 5 + b2] * w2j[b2][cc];
            hv[a][cc] = s;
        }

    for (int i = o0; i < o1; i++) {
        float w[5];
#pragma unroll
        for (int a = 0; a < 5; a++) w[a] = __ldg(W2 + a * 2048 + i);   // broadcast
        float vv[4];
#pragma unroll
        for (int cc = 0; cc < 4; cc++) {
            float s = 0.f;
#pragma unroll
            for (int a = 0; a < 5; a++) s += w[a] * hv[a][cc];
            vv[cc] = s;
        }
        const int d = i - jo;
        if ((unsigned)d < 4u) vv[d] += REPS;
        float4 v;
        v.x = vv[0]; v.y = vv[1]; v.z = vv[2]; v.w = vv[3];
        *reinterpret_cast<float4*>(out + (size_t)i * 2048 + jo) = v;
    }

    // ---------------- Epilogue: last finisher resets scratch ----------------
    __syncthreads();
    if (tid == 0) {
        __threadfence();
        if (atomicAdd(&g_done, 1u) == (unsigned)NBLK - 1u) {
#pragma unroll
            for (int e = 0; e < 25; e++) g_M[e * 32] = 0.f;
            g_cnt  = 0u;
            __threadfence();
            g_done = 0u;
        }
    }
}

// ---------------------------------------------------------------------------
extern "C" void kernel_launch(void* const* d_in, const int* in_sizes, int n_in,
                              void* d_out, int out_size) {
    const float* X  = (const float*)d_in[0];   // (1, 4096, 4096) f32
    const float* W1 = (const float*)d_in[1];   // (4096, 5) f32
    const float* W2 = (const float*)d_in[2];   // (5, 2048) f32
    float* out = (float*)d_out;                // (2048, 2048) f32

    k_all<<<NBLK, 256>>>(X, W1, W2, out);
}

// round 10
// speedup vs baseline: 1.0624x; 1.0624x over previous
#include <cuda_runtime.h>

#define REPS 1e-4f
#define GB   222                 // k_proj bands; grid (2, GB) = 444 blocks, 3/SM
#define NBLK_PROJ (2 * GB)

// Scratch (no allocations allowed). Zero-init at load; last k_proj block
// resets g_M/g_cnt after consuming, so graph replays see clean state.
__device__ float    g_M[25 * 32];  // each accumulator on its own 128B line
__device__ unsigned g_cnt;
__device__ float    g_H[5 * 2048]; // H = A5 @ W2, produced by last proj block

// ---- packed f32x2 helpers --------------------------------------------------
__device__ __forceinline__ unsigned long long ffma2(unsigned long long a,
                                                    unsigned long long b,
                                                    unsigned long long c) {
    unsigned long long d;
    asm("fma.rn.f32x2 %0, %1, %2, %3;" : "=l"(d) : "l"(a), "l"(b), "l"(c));
    return d;
}
__device__ __forceinline__ float2 unpack2(unsigned long long v) {
    float2 r;
    asm("mov.b64 {%0, %1}, %2;" : "=f"(r.x), "=f"(r.y) : "l"(v));
    return r;
}
__device__ __forceinline__ unsigned long long pack_dup(float v) {
    unsigned long long d;
    asm("mov.b64 %0, {%1, %1};" : "=l"(d) : "f"(v));
    return d;
}

// ---------------------------------------------------------------------------
// K1: t[j][a] = sum_i W1[i,a]*X[i,j]; fold M[a][b] += t[j][a]*W1[j,b] once.
// 8 COLS/THREAD as 4 f32x2 column-pairs + packed fma.rn.f32x2:
//   per row: 2 LDG.128 + 5 LDS.64 (dup-pair W1) + 20 FFMA2 for 32 bytes
// -> FMA-pipe, smem-crossbar and issue cost per byte all HALVED vs R4.
// Grid (2, 222) = 444 blocks, 3/SM (launch_bounds(256,3) -> <=84 regs, no
// spill for ~76 live), single wave. Band = 18-19 rows.
// Last block: thread 0 runs 5x5 Jacobi; 256 threads emit H = A5@W2.
// ---------------------------------------------------------------------------
__global__ __launch_bounds__(256, 3) void k_proj(const float* __restrict__ X,
                                                 const float* __restrict__ W1,
                                                 const float* __restrict__ W2) {
    const int tid = threadIdx.x;
    const int j0  = blockIdx.x * 2048 + tid * 8;
    const int r0  = (blockIdx.y * 4096) / GB;
    const int r1  = ((blockIdx.y + 1) * 4096) / GB;
    const int R   = r1 - r0;                      // 18 or 19

    __shared__ __align__(8) unsigned long long sW1d[19 * 5];  // (w,w) pairs
    __shared__ float sM[8][25];
    __shared__ float sA5[25];
    __shared__ bool  sLast;
    if (tid < R * 5) sW1d[tid] = pack_dup(W1[r0 * 5 + tid]);
    __syncthreads();

    // 4 column-pairs x 5 accumulators, packed f32x2 (40 regs)
    unsigned long long tacc[4][5];
#pragma unroll
    for (int p = 0; p < 4; p++)
#pragma unroll
        for (int a = 0; a < 5; a++) tacc[p][a] = 0ull;

    const float* Xb = X + (size_t)r0 * 4096 + j0;
#pragma unroll 2
    for (int r = 0; r < R; r++) {
        const ulonglong2 xa = *reinterpret_cast<const ulonglong2*>(Xb + (size_t)r * 4096);
        const ulonglong2 xb = *reinterpret_cast<const ulonglong2*>(Xb + (size_t)r * 4096 + 4);
        unsigned long long wd[5];
#pragma unroll
        for (int a = 0; a < 5; a++) wd[a] = sW1d[r * 5 + a];
#pragma unroll
        for (int a = 0; a < 5; a++) {
            tacc[0][a] = ffma2(xa.x, wd[a], tacc[0][a]);
            tacc[1][a] = ffma2(xa.y, wd[a], tacc[1][a]);
            tacc[2][a] = ffma2(xb.x, wd[a], tacc[2][a]);
            tacc[3][a] = ffma2(xb.y, wd[a], tacc[3][a]);
        }
    }

    // Fold with W1[j,b]: 8 columns, once per thread
    float mp[5][5];
#pragma unroll
    for (int a = 0; a < 5; a++)
#pragma unroll
        for (int b = 0; b < 5; b++) mp[a][b] = 0.f;
#pragma unroll
    for (int p = 0; p < 4; p++) {
        float tl[5], th[5];
#pragma unroll
        for (int a = 0; a < 5; a++) {
            const float2 t2 = unpack2(tacc[p][a]);
            tl[a] = t2.x; th[a] = t2.y;
        }
        const int jlo = j0 + 2 * p, jhi = jlo + 1;
        float wl[5], wh[5];
#pragma unroll
        for (int b = 0; b < 5; b++) {
            wl[b] = __ldg(W1 + jlo * 5 + b);
            wh[b] = __ldg(W1 + jhi * 5 + b);
        }
#pragma unroll
        for (int a = 0; a < 5; a++)
#pragma unroll
            for (int b = 0; b < 5; b++)
                mp[a][b] += tl[a] * wl[b] + th[a] * wh[b];
    }

    // Block reduce 25 values -> 25 padded global atomics
    const int lane = tid & 31, warp = tid >> 5;
#pragma unroll
    for (int e = 0; e < 25; e++) {
        float v = mp[e / 5][e % 5];
#pragma unroll
        for (int o = 16; o > 0; o >>= 1) v += __shfl_down_sync(0xffffffffu, v, o);
        if (lane == 0) sM[warp][e] = v;
    }
    __syncthreads();
    if (tid < 25) {
        float v = 0.f;
#pragma unroll
        for (int wq = 0; wq < 8; wq++) v += sM[wq][tid];
        atomicAdd(&g_M[tid * 32], v);
    }
    if (tid == 0) {
        __threadfence();
        sLast = (atomicAdd(&g_cnt, 1u) == (unsigned)NBLK_PROJ - 1u);
    }
    __syncthreads();
    if (!sLast) return;

    // ---- Last block. Thread 0: B = M*M^T ; Jacobi ; A5 -> shared ----
    if (tid == 0) {
        float m[5][5], b[5][5], u[5][5];
#pragma unroll
        for (int a = 0; a < 5; a++)
#pragma unroll
            for (int c = 0; c < 5; c++) m[a][c] = __ldcg(&g_M[(a * 5 + c) * 32]);

        float tr = 0.f;
#pragma unroll
        for (int a = 0; a < 5; a++)
#pragma unroll
            for (int c = 0; c < 5; c++) {
                float s = 0.f;
#pragma unroll
                for (int k = 0; k < 5; k++) s += m[a][k] * m[c][k];
                b[a][c] = s;
                u[a][c] = (a == c) ? 1.f : 0.f;
                if (a == c) tr += s;
            }
        const float skip_tol = 1e-7f * tr;

#pragma unroll
        for (int sweep = 0; sweep < 5; sweep++) {
#pragma unroll
            for (int p = 0; p < 4; p++) {
#pragma unroll
                for (int q = p + 1; q < 5; q++) {
                    const float apq = b[p][q];
                    if (fabsf(apq) > skip_tol) {
                        const float tau = (b[q][q] - b[p][p]) / (2.f * apq);
                        const float t   = copysignf(1.f, tau) / (fabsf(tau) + sqrtf(1.f + tau * tau));
                        const float c   = rsqrtf(1.f + t * t);
                        const float s   = t * c;
#pragma unroll
                        for (int k = 0; k < 5; k++) {
                            const float bkp = b[k][p], bkq = b[k][q];
                            b[k][p] = c * bkp - s * bkq;
                            b[k][q] = s * bkp + c * bkq;
                        }
#pragma unroll
                        for (int k = 0; k < 5; k++) {
                            const float bpk = b[p][k], bqk = b[q][k];
                            b[p][k] = c * bpk - s * bqk;
                            b[q][k] = s * bpk + c * bqk;
                            const float ukp = u[k][p], ukq = u[k][q];
                            u[k][p] = c * ukp - s * ukq;
                            u[k][q] = s * ukp + c * ukq;
                        }
                    }
                }
            }
        }

        float f[5];
#pragma unroll
        for (int d = 0; d < 5; d++) {
            const float lam = fmaxf(b[d][d], 0.f);
            f[d] = fmaxf(sqrtf(lam), REPS) - REPS;
        }
#pragma unroll
        for (int a = 0; a < 5; a++)
#pragma unroll
            for (int c = 0; c < 5; c++) {
                float s = 0.f;
#pragma unroll
                for (int d = 0; d < 5; d++) s += u[a][d] * f[d] * u[c][d];
                sA5[a * 5 + c] = s;
            }

        // Reset scratch for the next graph replay
#pragma unroll
        for (int e = 0; e < 25; e++) g_M[e * 32] = 0.f;
        g_cnt = 0u;
    }
    __syncthreads();

    // ---- All 256 threads: H[a][j] = sum_b A5[a][b] * W2[b][j] -> g_H ----
    float a5[5][5];
#pragma unroll
    for (int a = 0; a < 5; a++)
#pragma unroll
        for (int c = 0; c < 5; c++) a5[a][c] = sA5[a * 5 + c];
#pragma unroll
    for (int k = 0; k < 8; k++) {
        const int j = tid + 256 * k;
        float w2j[5];
#pragma unroll
        for (int b2 = 0; b2 < 5; b2++) w2j[b2] = __ldg(W2 + b2 * 2048 + j);
#pragma unroll
        for (int a = 0; a < 5; a++) {
            float s = 0.f;
#pragma unroll
            for (int b2 = 0; b2 < 5; b2++) s += a5[a][b2] * w2j[b2];
            g_H[a * 2048 + j] = s;
        }
    }
}

// ---------------------------------------------------------------------------
// K2 (R6 variant — fastest measured): z[i][j] = sum_a W2[a,i]*H[a,j]+EPS*I.
// W2 band slice staged in smem as duplicated pairs ONCE; inner row loop is
// 5 LDS.64 + 10 fma.rn.f32x2 + STG.128 — zero LDG.
// ---------------------------------------------------------------------------
__global__ __launch_bounds__(256, 4) void k_out(const float* __restrict__ W2,
                                                float* __restrict__ out) {
    const int tid = threadIdx.x;
    const int jo  = blockIdx.x * 1024 + tid * 4;
    const int o0  = (blockIdx.y * 2048) / 296;
    const int o1  = ((blockIdx.y + 1) * 2048) / 296;
    const int RR  = o1 - o0;                      // 6 or 7

    __shared__ __align__(8) unsigned long long sW2d[8 * 5];  // (w,w) per row,a
    if (tid < RR * 5) {
        const int rr = tid / 5, a = tid % 5;
        sW2d[tid] = pack_dup(__ldg(W2 + a * 2048 + o0 + rr));
    }

    ulonglong2 h[5];
#pragma unroll
    for (int a = 0; a < 5; a++)
        h[a] = *reinterpret_cast<const ulonglong2*>(g_H + a * 2048 + jo);
    __syncthreads();

    for (int rr = 0; rr < RR; rr++) {
        const int i = o0 + rr;
        unsigned long long wd[5];
#pragma unroll
        for (int a = 0; a < 5; a++) wd[a] = sW2d[rr * 5 + a];

        unsigned long long vlo = 0ull, vhi = 0ull;
#pragma unroll
        for (int a = 0; a < 5; a++) {
            vlo = ffma2(wd[a], h[a].x, vlo);
            vhi = ffma2(wd[a], h[a].y, vhi);
        }
        const float2 flo = unpack2(vlo);
        const float2 fhi = unpack2(vhi);
        float4 v;
        v.x = flo.x; v.y = flo.y; v.z = fhi.x; v.w = fhi.y;

        const int d = i - jo;
        if ((unsigned)d < 4u) {
            if (d == 0) v.x += REPS;
            else if (d == 1) v.y += REPS;
            else if (d == 2) v.z += REPS;
            else v.w += REPS;
        }
        *reinterpret_cast<float4*>(out + (size_t)i * 2048 + jo) = v;
    }
}

// ---------------------------------------------------------------------------
extern "C" void kernel_launch(void* const* d_in, const int* in_sizes, int n_in,
                              void* d_out, int out_size) {
    const float* X  = (const float*)d_in[0];   // (1, 4096, 4096) f32
    const float* W1 = (const float*)d_in[1];   // (4096, 5) f32
    const float* W2 = (const float*)d_in[2];   // (5, 2048) f32
    float* out = (float*)d_out;                // (2048, 2048) f32

    k_proj<<<dim3(2, GB), 256>>>(X, W1, W2);
    k_out <<<dim3(2, 296), 256>>>(W2, out);
}